// round 3
// baseline (speedup 1.0000x reference)
#include <cuda_runtime.h>
#include <cstdint>

typedef unsigned long long ull;

#define HARD_CUT 6.5f
#define PI_F 3.14159265358979f
#define BM 128
#define BKK 16

// ---------------- scratch (static __device__ — no allocations) ----------------
// env: [20096 x 1600] (padded to full GEMM tiles; rows 20000..20095 never stored/read by epilogue)
__device__ __align__(16) float g_env[20096 * 1600];
__device__ __align__(16) float g_w2[1600 * 80];   // W2[k=s*80+f][o]
__device__ __align__(16) float g_C[20000 * 80];   // C[(a*4+c)][o]

__device__ __forceinline__ void ffma2(ull &d, ull a, ull b) {
    asm("fma.rn.f32x2 %0, %1, %2, %0;" : "+l"(d) : "l"(a), "l"(b));
}

__device__ __forceinline__ int lower_bound_i(const int* __restrict__ arr, int n, int val) {
    int lo = 0, hi = n;
    while (lo < hi) {
        int mid = (lo + hi) >> 1;
        if (arr[mid] < val) lo = mid + 1; else hi = mid;
    }
    return lo;
}

// ---------------- K0: transpose int_weights [20,80,80] (s,o,f) -> W2 [1600,80] ----------------
__global__ void transpose_w_kernel(const float* __restrict__ iw) {
    int idx = blockIdx.x * blockDim.x + threadIdx.x;
    if (idx < 1600 * 80) {
        int k = idx / 80, o = idx % 80;
        int s = k / 80, f = k % 80;
        g_w2[idx] = iw[s * 6400 + o * 80 + f];
    }
}

// ---------------- K1: segmented envsum ----------------
// Block per atom. 320 threads. Per chunk of 8 pairs: stage coef[8][80], feat[8][80] in smem,
// then each thread accumulates a 5(cs) x 4(f) register tile over the chunk.
__global__ __launch_bounds__(320) void envsum_kernel(
    const float* __restrict__ feat, const float* __restrict__ dist,
    const float* __restrict__ coord, const float* __restrict__ mu,
    const float* __restrict__ sigma, const int* __restrict__ pf,
    const int* __restrict__ ps, int n_pairs)
{
    __shared__ __align__(16) float s_coef[8][80];
    __shared__ __align__(16) float s_feat[8][80];

    int a   = blockIdx.x;
    int tid = threadIdx.x;
    int start = lower_bound_i(pf, n_pairs, a);
    int end   = lower_bound_i(pf, n_pairs, a + 1);

    int fg  = tid % 20;  int f0  = fg * 4;     // f tile: 4 consecutive features
    int csg = tid / 20;  int cs0 = csg * 5;    // cs tile: 5 consecutive (c*20+s)

    // producer role: pair pp (0..7) within chunk, lane j (0..39) computes 2 coef entries
    int pp = tid / 40;
    int j  = tid % 40;
    int cc = j / 10;            // channel 0..3 (0=scalar, 1..3 = x,y,z)
    int sb = (j % 10) * 2;      // s base (even)
    float mu0 = mu[sb],     mu1 = mu[sb + 1];
    float is0 = 1.0f / sigma[sb], is1 = 1.0f / sigma[sb + 1];

    float acc[5][4];
    #pragma unroll
    for (int i = 0; i < 5; i++)
        #pragma unroll
        for (int q = 0; q < 4; q++) acc[i][q] = 0.0f;

    int nchunk = (end - start + 7) >> 3;
    for (int ch = 0; ch < nchunk; ch++) {
        int p0  = start + ch * 8;
        int cnt = min(8, end - p0);
        if (pp < cnt) {
            int p = p0 + pp;
            float d   = dist[p];
            float inv = 1.0f / d;
            float cut = (d < HARD_CUT) ? 0.5f * (__cosf(PI_F * d * (1.0f / HARD_CUT)) + 1.0f) : 0.0f;
            float wc = 1.0f;
            if (cc > 0) wc = coord[p * 3 + (cc - 1)] * inv;
            float cw = cut * wc;
            float z0 = (inv - mu0) * is0;
            float z1 = (inv - mu1) * is1;
            s_coef[pp][cc * 20 + sb    ] = __expf(-0.5f * z0 * z0) * cw;
            s_coef[pp][cc * 20 + sb + 1] = __expf(-0.5f * z1 * z1) * cw;
            if (j < 20) {
                float4 v = *((const float4*)feat + ps[p] * 20 + j);
                *(float4*)&s_feat[pp][j * 4] = v;
            }
        }
        __syncthreads();
        for (int p = 0; p < cnt; p++) {
            float4 fv = *(const float4*)&s_feat[p][f0];
            #pragma unroll
            for (int i = 0; i < 5; i++) {
                float cf = s_coef[p][cs0 + i];
                acc[i][0] = fmaf(cf, fv.x, acc[i][0]);
                acc[i][1] = fmaf(cf, fv.y, acc[i][1]);
                acc[i][2] = fmaf(cf, fv.z, acc[i][2]);
                acc[i][3] = fmaf(cf, fv.w, acc[i][3]);
            }
        }
        __syncthreads();
    }

    // cs0..cs0+4 stays within one channel block (cs0 % 20 in {0,5,10,15})
    int c     = cs0 / 20;
    int sbase = cs0 % 20;
    int rbase = (a * 4 + c) * 1600;
    #pragma unroll
    for (int i = 0; i < 5; i++) {
        *(float4*)&g_env[rbase + (sbase + i) * 80 + f0] =
            make_float4(acc[i][0], acc[i][1], acc[i][2], acc[i][3]);
    }
}

// ---------------- K2: C[20000x80] = env[20000x1600] @ W2[1600x80], packed f32x2 FMA ----------------
// 256 threads, BM=128, BN=80, BK=16. Microtile 8(m) x 5(n) per thread, m packed in pairs.
// As is k-major with XOR swizzle (conflict-free transposed stores); Bs holds pre-duplicated (b,b) pairs.
__global__ __launch_bounds__(256) void gemm_kernel(int M) {
    __shared__ __align__(16) float As[BKK * BM];
    __shared__ __align__(16) float Bs[BKK * 80 * 2];

    int tid = threadIdx.x;
    int m0blk = blockIdx.x * BM;
    int tm = tid >> 4, tn = tid & 15;
    int mb = tm * 8, n0 = tn * 5;

    ull acc[4][5];
    #pragma unroll
    for (int i = 0; i < 4; i++)
        #pragma unroll
        for (int jj = 0; jj < 5; jj++) acc[i][jj] = 0ull;

    // A tile loader: thread -> rows (tid>>2) and (tid>>2)+64, k-quad (tid&3)*4
    int aRow0 = m0blk + (tid >> 2);
    int aRow1 = aRow0 + 64;
    int aK    = (tid & 3) * 4;
    int sw    = (tid & 3) * 8;                 // == ((k>>2)&3)*8 for k in [aK, aK+3]
    int sAs0  = aK * BM + ((tid >> 2) ^ sw);
    int sAs1  = aK * BM + (((tid >> 2) + 64) ^ sw);

    float4 fa0, fa1; float fb[5];
    fa0 = *(const float4*)&g_env[aRow0 * 1600 + aK];
    fa1 = *(const float4*)&g_env[aRow1 * 1600 + aK];
    #pragma unroll
    for (int it = 0; it < 5; it++) fb[it] = g_w2[tid + it * 256];

    for (int k0 = 0; k0 < 1600; k0 += BKK) {
        // commit staged tile to smem
        As[sAs0         ] = fa0.x;
        As[sAs0 +     BM] = fa0.y;
        As[sAs0 + 2 * BM] = fa0.z;
        As[sAs0 + 3 * BM] = fa0.w;
        As[sAs1         ] = fa1.x;
        As[sAs1 +     BM] = fa1.y;
        As[sAs1 + 2 * BM] = fa1.z;
        As[sAs1 + 3 * BM] = fa1.w;
        #pragma unroll
        for (int it = 0; it < 5; it++) {
            int idx = tid + it * 256;          // = r*80 + c, r<16
            unsigned u = __float_as_uint(fb[it]);
            ull bb = ((ull)u << 32) | (ull)u;
            *(ull*)&Bs[idx * 2] = bb;
        }
        __syncthreads();

        // prefetch next tile into registers (hidden behind compute)
        int k0n = k0 + BKK;
        if (k0n < 1600) {
            fa0 = *(const float4*)&g_env[aRow0 * 1600 + k0n + aK];
            fa1 = *(const float4*)&g_env[aRow1 * 1600 + k0n + aK];
            #pragma unroll
            for (int it = 0; it < 5; it++) {
                int idx = tid + it * 256;
                fb[it] = g_w2[(k0n + idx / 80) * 80 + idx % 80];
            }
        }

        #pragma unroll
        for (int k = 0; k < BKK; k++) {
            int sw8 = ((k >> 2) & 3) * 8;
            ull av[4], bv[5];
            #pragma unroll
            for (int i = 0; i < 4; i++)
                av[i] = *(const ull*)&As[k * BM + ((mb + 2 * i) ^ sw8)];
            #pragma unroll
            for (int jj = 0; jj < 5; jj++)
                bv[jj] = *(const ull*)&Bs[(k * 80 + n0 + jj) * 2];
            #pragma unroll
            for (int i = 0; i < 4; i++)
                #pragma unroll
                for (int jj = 0; jj < 5; jj++)
                    ffma2(acc[i][jj], av[i], bv[jj]);
        }
        __syncthreads();
    }

    #pragma unroll
    for (int i = 0; i < 4; i++) {
        int gm = m0blk + mb + 2 * i;
        #pragma unroll
        for (int jj = 0; jj < 5; jj++) {
            ull v = acc[i][jj];
            if (gm < M)     g_C[gm * 80 + n0 + jj]       = __uint_as_float((unsigned)(v & 0xffffffffull));
            if (gm + 1 < M) g_C[(gm + 1) * 80 + n0 + jj] = __uint_as_float((unsigned)(v >> 32));
        }
    }
}

// ---------------- K3: epilogue (vector norm + self interaction + bias) ----------------
// 32 atoms / block, 256 threads, microtile 2(a) x 5(o).
__global__ __launch_bounds__(256) void epilogue_kernel(
    const float* __restrict__ feat, const float* __restrict__ selfw,
    const float* __restrict__ selfb, const float* __restrict__ vecs,
    float* __restrict__ out, int n_atoms)
{
    __shared__ float s_w[80 * 81];   // padded stride 81 -> conflict-free
    __shared__ float s_f[32 * 80];

    int tid = threadIdx.x;
    int aBase = blockIdx.x * 32;

    for (int idx = tid; idx < 6400; idx += 256)
        s_w[(idx / 80) * 81 + idx % 80] = selfw[idx];
    for (int idx = tid; idx < 2560; idx += 256) {
        int ga = aBase + idx / 80;
        s_f[idx] = (ga < n_atoms) ? feat[ga * 80 + idx % 80] : 0.0f;
    }
    __syncthreads();

    int ta = tid >> 4, to = tid & 15;
    int a0 = ta * 2, o0 = to * 5;

    float acc[2][5];
    #pragma unroll
    for (int ja = 0; ja < 2; ja++)
        #pragma unroll
        for (int jo = 0; jo < 5; jo++) acc[ja][jo] = 0.0f;

    for (int i = 0; i < 80; i++) {
        float fv0 = s_f[a0 * 80 + i];
        float fv1 = s_f[(a0 + 1) * 80 + i];
        #pragma unroll
        for (int jo = 0; jo < 5; jo++) {
            float w = s_w[(o0 + jo) * 81 + i];
            acc[0][jo] = fmaf(fv0, w, acc[0][jo]);
            acc[1][jo] = fmaf(fv1, w, acc[1][jo]);
        }
    }

    #pragma unroll
    for (int ja = 0; ja < 2; ja++) {
        int ga = aBase + a0 + ja;
        if (ga < n_atoms) {
            int rb = ga * 4 * 80;
            #pragma unroll
            for (int jo = 0; jo < 5; jo++) {
                int o = o0 + jo;
                float c0 = g_C[rb + o];
                float cx = g_C[rb + 80 + o];
                float cy = g_C[rb + 160 + o];
                float cz = g_C[rb + 240 + o];
                out[ga * 80 + o] = c0 + acc[ja][jo] + selfb[o]
                    + vecs[o] * sqrtf(fmaf(cx, cx, fmaf(cy, cy, cz * cz)) + 1e-30f);
            }
        }
    }
}

// ---------------- launch ----------------
extern "C" void kernel_launch(void* const* d_in, const int* in_sizes, int n_in,
                              void* d_out, int out_size) {
    const float* feat  = (const float*)d_in[0];
    const float* dist  = (const float*)d_in[1];
    const float* coord = (const float*)d_in[2];
    const float* iw    = (const float*)d_in[3];
    const float* selfw = (const float*)d_in[4];
    const float* selfb = (const float*)d_in[5];
    const float* vecs  = (const float*)d_in[6];
    const float* mu    = (const float*)d_in[7];
    const float* sigma = (const float*)d_in[8];
    const int*   pf    = (const int*)d_in[9];
    const int*   ps    = (const int*)d_in[10];
    int n_pairs = in_sizes[9];
    int n_atoms = in_sizes[0] / 80;
    float* out = (float*)d_out;

    transpose_w_kernel<<<(1600 * 80 + 255) / 256, 256>>>(iw);
    envsum_kernel<<<n_atoms, 320>>>(feat, dist, coord, mu, sigma, pf, ps, n_pairs);
    int M = n_atoms * 4;
    gemm_kernel<<<(M + BM - 1) / BM, 256>>>(M);
    epilogue_kernel<<<(n_atoms + 31) / 32, 256>>>(feat, selfw, selfb, vecs, out, n_atoms);
}

// round 4
// speedup vs baseline: 1.2655x; 1.2655x over previous
#include <cuda_runtime.h>
#include <cstdint>

typedef unsigned long long ull;

#define HARD_CUT 6.5f
#define PI_F 3.14159265358979f

#define KTOT   1680          // 20*80 scalar K  + 80 self-interaction rows
#define MPAD   20096         // 157 * 128
#define BM     128
#define BK     16
#define KSPLIT 5
#define NITER  21            // 105 BK-iters / KSPLIT

// ---------------- scratch (static __device__ — no allocations) ----------------
__device__ __align__(16) float g_env[MPAD * KTOT];          // ~135 MB
__device__ __align__(16) float g_w2[KTOT * 80];             // W2[k][o]
__device__ __align__(16) float g_Cp[KSPLIT * MPAD * 80];    // K-split partials

__device__ __forceinline__ void ffma2(ull &d, ull a, ull b) {
    asm("fma.rn.f32x2 %0, %1, %2, %0;" : "+l"(d) : "l"(a), "l"(b));
}
__device__ __forceinline__ ull dup2(float v) {
    ull d;
    asm("mov.b64 %0, {%1, %1};" : "=l"(d) : "r"(__float_as_uint(v)));
    return d;
}
__device__ __forceinline__ float2 unpack2(ull v) {
    return make_float2(__uint_as_float((unsigned)(v & 0xffffffffull)),
                       __uint_as_float((unsigned)(v >> 32)));
}
__device__ __forceinline__ int lower_bound_i(const int* __restrict__ arr, int n, int val) {
    int lo = 0, hi = n;
    while (lo < hi) { int mid = (lo + hi) >> 1; if (arr[mid] < val) lo = mid + 1; else hi = mid; }
    return lo;
}

// ---------------- K0: build W2 [1680 x 80]: rows 0..1599 from int_weights, 1600..1679 from selfw ----------------
__global__ void transpose_w_kernel(const float* __restrict__ iw, const float* __restrict__ selfw) {
    int idx = blockIdx.x * blockDim.x + threadIdx.x;
    if (idx < KTOT * 80) {
        int k = idx / 80, o = idx % 80;
        float v;
        if (k < 1600) { int s = k / 80, f = k % 80; v = iw[s * 6400 + o * 80 + f]; }
        else          { int f = k - 1600;           v = selfw[o * 80 + f]; }
        g_w2[idx] = v;
    }
}

// ---------------- K1: segmented envsum (double-buffered producer, f32x2 consumer) ----------------
// Block per atom, 320 threads. Consumer tile: 2 cs x 10 f per thread (f packed in pairs).
__global__ __launch_bounds__(320) void envsum_kernel(
    const float* __restrict__ feat, const float* __restrict__ dist,
    const float* __restrict__ coord, const float* __restrict__ mu,
    const float* __restrict__ sigma, const int* __restrict__ pf,
    const int* __restrict__ ps, int n_pairs)
{
    __shared__ __align__(16) float s_coef[8][80];
    __shared__ __align__(16) float s_feat[8][80];

    int a   = blockIdx.x;
    int tid = threadIdx.x;
    int start = lower_bound_i(pf, n_pairs, a);
    int end   = lower_bound_i(pf, n_pairs, a + 1);

    // consumer roles
    int csg = tid >> 3;  int cs0 = csg * 2;    // 40 cs-groups x 2
    int fg  = tid & 7;   int f0  = fg * 10;    // 8 f-groups x 10

    // producer roles: pair pp (0..7), lane j (0..39) -> 2 coef entries
    int pp = tid / 40;
    int j  = tid % 40;
    int cc = j / 10;
    int sb = (j % 10) * 2;
    float mu0 = mu[sb],          mu1 = mu[sb + 1];
    float is0 = 1.0f / sigma[sb], is1 = 1.0f / sigma[sb + 1];

    ull acc[2][5];
    #pragma unroll
    for (int i = 0; i < 2; i++)
        #pragma unroll
        for (int u = 0; u < 5; u++) acc[i][u] = 0ull;

    int nchunk = (end - start + 7) >> 3;

    // register prefetch buffers
    float nd = 1.0f, ncd = 0.0f;
    float4 nf = make_float4(0.f, 0.f, 0.f, 0.f);
    int have = 0;

    // prefetch chunk 0
    if (nchunk > 0 && pp < min(8, end - start)) {
        int p = start + pp;
        nd  = dist[p];
        if (cc > 0) ncd = coord[p * 3 + (cc - 1)];
        if (j < 20) { int r = ps[p]; nf = ((const float4*)feat)[r * 20 + j]; }
        have = 1;
    }

    for (int ch = 0; ch < nchunk; ch++) {
        __syncthreads();   // consumers done with previous chunk's smem
        if (have) {
            float d   = nd;
            float inv = 1.0f / d;
            float cut = (d < HARD_CUT) ? 0.5f * (__cosf(PI_F * d * (1.0f / HARD_CUT)) + 1.0f) : 0.0f;
            float wc  = (cc > 0) ? ncd * inv : 1.0f;
            float cw  = cut * wc;
            float z0 = (inv - mu0) * is0;
            float z1 = (inv - mu1) * is1;
            s_coef[pp][cc * 20 + sb    ] = __expf(-0.5f * z0 * z0) * cw;
            s_coef[pp][cc * 20 + sb + 1] = __expf(-0.5f * z1 * z1) * cw;
            if (j < 20) *(float4*)&s_feat[pp][j * 4] = nf;
        }
        int cnt = min(8, end - (start + ch * 8));
        __syncthreads();

        // prefetch chunk ch+1 (LDG latency overlaps the consume loop below)
        have = 0;
        if (ch + 1 < nchunk) {
            int p0 = start + (ch + 1) * 8;
            if (pp < min(8, end - p0)) {
                int p = p0 + pp;
                nd  = dist[p];
                if (cc > 0) ncd = coord[p * 3 + (cc - 1)];
                if (j < 20) { int r = ps[p]; nf = ((const float4*)feat)[r * 20 + j]; }
                have = 1;
            }
        }

        for (int p = 0; p < cnt; p++) {
            float2 cf = *(const float2*)&s_coef[p][cs0];
            ull c0d = dup2(cf.x);
            ull c1d = dup2(cf.y);
            #pragma unroll
            for (int u = 0; u < 5; u++) {
                ull fv = *(const ull*)&s_feat[p][f0 + 2 * u];
                ffma2(acc[0][u], c0d, fv);
                ffma2(acc[1][u], c1d, fv);
            }
        }
    }

    // store: cs0 even and 20 even -> both cs share one channel
    int c  = cs0 / 20;
    int s0 = cs0 % 20;
    int rbase = (a * 4 + c) * KTOT;
    #pragma unroll
    for (int i = 0; i < 2; i++) {
        int cb = rbase + (s0 + i) * 80 + f0;
        #pragma unroll
        for (int u = 0; u < 5; u++)
            *(float2*)&g_env[cb + 2 * u] = unpack2(acc[i][u]);
    }

    // self-interaction fold: env[(a,c), 1600+f] = (c==0) ? feat[a,f] : 0
    {
        int c2 = tid / 80;            // exactly 320 threads -> c2 in 0..3
        int f  = tid % 80;
        g_env[(a * 4 + c2) * KTOT + 1600 + f] = (c2 == 0) ? feat[a * 80 + f] : 0.0f;
    }
}

// ---------------- K2: K-split GEMM, N-packed f32x2 ----------------
// grid (157, KSPLIT), 256 threads. Tile per thread: 4 m x 10 n (n packed in pairs).
__global__ __launch_bounds__(256, 2) void gemm_kernel(int M) {
    __shared__ __align__(16) float As[BK * BM];   // [k][m ^ swz(k)]
    __shared__ __align__(16) float Bs[BK * 80];

    int tid   = threadIdx.x;
    int m0blk = blockIdx.x * BM;
    int ksOff = blockIdx.y * (NITER * BK);

    int tm = tid >> 3, tn = tid & 7;
    int m0 = tm * 4,   n0 = tn * 10;

    // A loader: rows (tid>>2) and +64, k-quad (tid&3)*4; swizzle = ((k>>2)&3)*4 = (tid&3)*4
    int row0 = tid >> 2, row1 = row0 + 64;
    int aK   = (tid & 3) * 4;
    int sw   = (tid & 3) * 4;
    const float* aP0 = &g_env[(m0blk + row0) * KTOT + ksOff + aK];
    const float* aP1 = &g_env[(m0blk + row1) * KTOT + ksOff + aK];
    int sA0 = aK * BM + (row0 ^ sw);
    int sA1 = aK * BM + (row1 ^ sw);

    ull acc[4][5];
    #pragma unroll
    for (int i = 0; i < 4; i++)
        #pragma unroll
        for (int u = 0; u < 5; u++) acc[i][u] = 0ull;

    float4 fa0 = *(const float4*)aP0;
    float4 fa1 = *(const float4*)aP1;
    float fb[5];
    #pragma unroll
    for (int it = 0; it < 5; it++) {
        int idx = tid + it * 256;
        fb[it] = g_w2[(ksOff + idx / 80) * 80 + idx % 80];
    }

    for (int kt = 0; kt < NITER; kt++) {
        __syncthreads();
        As[sA0         ] = fa0.x;
        As[sA0 +     BM] = fa0.y;
        As[sA0 + 2 * BM] = fa0.z;
        As[sA0 + 3 * BM] = fa0.w;
        As[sA1         ] = fa1.x;
        As[sA1 +     BM] = fa1.y;
        As[sA1 + 2 * BM] = fa1.z;
        As[sA1 + 3 * BM] = fa1.w;
        #pragma unroll
        for (int it = 0; it < 5; it++) Bs[tid + it * 256] = fb[it];
        __syncthreads();

        if (kt + 1 < NITER) {
            int kb = ksOff + (kt + 1) * BK;
            fa0 = *(const float4*)(aP0 + (kt + 1) * BK);
            fa1 = *(const float4*)(aP1 + (kt + 1) * BK);
            #pragma unroll
            for (int it = 0; it < 5; it++) {
                int idx = tid + it * 256;
                fb[it] = g_w2[(kb + idx / 80) * 80 + idx % 80];
            }
        }

        #pragma unroll
        for (int k = 0; k < BK; k++) {
            int swk = ((k >> 2) & 3) * 4;
            float4 am = *(const float4*)&As[k * BM + (m0 ^ swk)];
            ull a0 = dup2(am.x), a1 = dup2(am.y), a2 = dup2(am.z), a3 = dup2(am.w);
            ull bv[5];
            #pragma unroll
            for (int u = 0; u < 5; u++)
                bv[u] = *(const ull*)&Bs[k * 80 + n0 + 2 * u];
            #pragma unroll
            for (int u = 0; u < 5; u++) {
                ffma2(acc[0][u], a0, bv[u]);
                ffma2(acc[1][u], a1, bv[u]);
                ffma2(acc[2][u], a2, bv[u]);
                ffma2(acc[3][u], a3, bv[u]);
            }
        }
    }

    float* cp = g_Cp + blockIdx.y * (MPAD * 80);
    #pragma unroll
    for (int i = 0; i < 4; i++) {
        int gm = m0blk + m0 + i;
        if (gm < M) {
            #pragma unroll
            for (int u = 0; u < 5; u++)
                *(float2*)&cp[gm * 80 + n0 + 2 * u] = unpack2(acc[i][u]);
        }
    }
}

// ---------------- K3: epilogue — sum K-split partials, vector norm, bias ----------------
__global__ void epilogue_kernel(const float* __restrict__ selfb, const float* __restrict__ vecs,
                                float* __restrict__ out, int total) {
    int idx = blockIdx.x * blockDim.x + threadIdx.x;
    if (idx >= total) return;
    int a = idx / 80, o = idx % 80;
    float s = 0.f, x = 0.f, y = 0.f, z = 0.f;
    #pragma unroll
    for (int ks = 0; ks < KSPLIT; ks++) {
        const float* cp = g_Cp + ks * (MPAD * 80) + (a * 4) * 80 + o;
        s += cp[0];
        x += cp[80];
        y += cp[160];
        z += cp[240];
    }
    out[idx] = s + selfb[o] + vecs[o] * sqrtf(fmaf(x, x, fmaf(y, y, z * z)) + 1e-30f);
}

// ---------------- launch ----------------
extern "C" void kernel_launch(void* const* d_in, const int* in_sizes, int n_in,
                              void* d_out, int out_size) {
    const float* feat  = (const float*)d_in[0];
    const float* dist  = (const float*)d_in[1];
    const float* coord = (const float*)d_in[2];
    const float* iw    = (const float*)d_in[3];
    const float* selfw = (const float*)d_in[4];
    const float* selfb = (const float*)d_in[5];
    const float* vecs  = (const float*)d_in[6];
    const float* mu    = (const float*)d_in[7];
    const float* sigma = (const float*)d_in[8];
    const int*   pf    = (const int*)d_in[9];
    const int*   ps    = (const int*)d_in[10];
    int n_pairs = in_sizes[9];
    int n_atoms = in_sizes[0] / 80;
    float* out = (float*)d_out;

    transpose_w_kernel<<<(KTOT * 80 + 255) / 256, 256>>>(iw, selfw);
    envsum_kernel<<<n_atoms, 320>>>(feat, dist, coord, mu, sigma, pf, ps, n_pairs);
    int M = n_atoms * 4;
    dim3 ggrid((M + BM - 1) / BM, KSPLIT);
    gemm_kernel<<<ggrid, 256>>>(M);
    int total = n_atoms * 80;
    epilogue_kernel<<<(total + 255) / 256, 256>>>(selfb, vecs, out, total);
}

// round 6
// speedup vs baseline: 1.6027x; 1.2664x over previous
#include <cuda_runtime.h>
#include <cuda_bf16.h>
#include <cstdint>

typedef unsigned long long ull;

#define HARD_CUT 6.5f
#define PI_F 3.14159265358979f

#define KTOT 1728            // 1600 scalar + 80 self + 48 zero pad (27*64)
#define KCH  64
#define NCH  27
#define MPAD 20096           // 157*128

// smem stage layout (bytes, per buffer)
#define OFF_AH 0
#define OFF_AL 16384
#define OFF_BH 32768
#define OFF_BL 43008
#define STG_BYTES 53248

// ---------------- scratch (static __device__, zero-init => pad rows/cols stay 0) ----
__device__ __align__(16) __nv_bfloat16 g_env_hi[(size_t)MPAD * KTOT];
__device__ __align__(16) __nv_bfloat16 g_env_lo[(size_t)MPAD * KTOT];
__device__ __align__(16) __nv_bfloat16 g_w2h[80 * KTOT];   // B[N=80][K] K-major
__device__ __align__(16) __nv_bfloat16 g_w2l[80 * KTOT];

// ---------------- helpers ----------------
__device__ __forceinline__ void ffma2(ull &d, ull a, ull b) {
    asm("fma.rn.f32x2 %0, %1, %2, %0;" : "+l"(d) : "l"(a), "l"(b));
}
__device__ __forceinline__ ull dup2(float v) {
    ull d; asm("mov.b64 %0, {%1, %1};" : "=l"(d) : "r"(__float_as_uint(v))); return d;
}
__device__ __forceinline__ float2 unpack2(ull v) {
    return make_float2(__uint_as_float((unsigned)(v & 0xffffffffull)),
                       __uint_as_float((unsigned)(v >> 32)));
}
__device__ __forceinline__ int lower_bound_i(const int* __restrict__ arr, int n, int val) {
    int lo = 0, hi = n;
    while (lo < hi) { int mid = (lo + hi) >> 1; if (arr[mid] < val) lo = mid + 1; else hi = mid; }
    return lo;
}
__device__ __forceinline__ uint32_t smem_u32(const void* p) {
    uint32_t a;
    asm("{ .reg .u64 t; cvta.to.shared.u64 t, %1; cvt.u32.u64 %0, t; }" : "=r"(a) : "l"(p));
    return a;
}
__device__ __forceinline__ void ldsm4(unsigned* r, uint32_t addr) {
    asm volatile("ldmatrix.sync.aligned.m8n8.x4.shared.b16 {%0,%1,%2,%3}, [%4];"
        : "=r"(r[0]), "=r"(r[1]), "=r"(r[2]), "=r"(r[3]) : "r"(addr));
}
__device__ __forceinline__ void ldsm2(unsigned* r, uint32_t addr) {
    asm volatile("ldmatrix.sync.aligned.m8n8.x2.shared.b16 {%0,%1}, [%2];"
        : "=r"(r[0]), "=r"(r[1]) : "r"(addr));
}
__device__ __forceinline__ void mma16816(float* d, const unsigned* a, const unsigned* b) {
    asm volatile("mma.sync.aligned.m16n8k16.row.col.f32.bf16.bf16.f32 "
        "{%0,%1,%2,%3}, {%4,%5,%6,%7}, {%8,%9}, {%0,%1,%2,%3};"
        : "+f"(d[0]), "+f"(d[1]), "+f"(d[2]), "+f"(d[3])
        : "r"(a[0]), "r"(a[1]), "r"(a[2]), "r"(a[3]), "r"(b[0]), "r"(b[1]));
}
#define CP16(dst, src)  asm volatile("cp.async.cg.shared.global [%0], [%1], 16;" :: "r"(dst), "l"(src) : "memory")
#define CP_COMMIT()     asm volatile("cp.async.commit_group;" ::: "memory")
#define CP_WAIT1()      asm volatile("cp.async.wait_group 1;" ::: "memory")
#define CP_WAIT0()      asm volatile("cp.async.wait_group 0;" ::: "memory")

// ---------------- K0: W2 -> bf16 hi/lo, [80 o][1728 k] K-major ----------------
__global__ void build_w_kernel(const float* __restrict__ iw, const float* __restrict__ selfw) {
    int idx = blockIdx.x * blockDim.x + threadIdx.x;
    if (idx >= 80 * KTOT) return;
    int o = idx / KTOT, k = idx % KTOT;
    float v = 0.0f;
    if (k < 1600)      { int s = k / 80, f = k % 80; v = iw[s * 6400 + o * 80 + f]; }
    else if (k < 1680) { v = selfw[o * 80 + (k - 1600)]; }
    __nv_bfloat16 h = __float2bfloat16(v);
    __nv_bfloat16 l = __float2bfloat16(v - __bfloat162float(h));
    g_w2h[idx] = h;
    g_w2l[idx] = l;
}

// ---------------- K1: segmented envsum -> bf16 hi/lo env ----------------
__global__ __launch_bounds__(320) void envsum_kernel(
    const float* __restrict__ feat, const float* __restrict__ dist,
    const float* __restrict__ coord, const float* __restrict__ mu,
    const float* __restrict__ sigma, const int* __restrict__ pf,
    const int* __restrict__ ps, int n_pairs)
{
    __shared__ __align__(16) float s_coef[16][80];
    __shared__ __align__(16) float s_feat[16][80];

    int a   = blockIdx.x;
    int tid = threadIdx.x;
    int start = lower_bound_i(pf, n_pairs, a);
    int end   = lower_bound_i(pf, n_pairs, a + 1);

    int csg = tid >> 3;  int cs0 = csg * 2;
    int fg  = tid & 7;   int f0  = fg * 10;

    int pp = tid / 20;
    int j  = tid - pp * 20;
    float muj = mu[j];
    float isj = 1.0f / sigma[j];

    ull acc[2][5];
    #pragma unroll
    for (int i = 0; i < 2; i++)
        #pragma unroll
        for (int u = 0; u < 5; u++) acc[i][u] = 0ull;

    int nchunk = (end - start + 15) >> 4;

    float nd = 1.0f, nx = 0.f, ny = 0.f, nz = 0.f;
    float4 nf = make_float4(0.f, 0.f, 0.f, 0.f);
    int have = 0;
    if (nchunk > 0 && pp < min(16, end - start)) {
        int p = start + pp;
        nd = dist[p]; nx = coord[3 * p]; ny = coord[3 * p + 1]; nz = coord[3 * p + 2];
        int r = ps[p]; nf = ((const float4*)feat)[r * 20 + j];
        have = 1;
    }

    for (int ch = 0; ch < nchunk; ch++) {
        __syncthreads();
        if (have) {
            float d   = nd;
            float inv = 1.0f / d;
            float cut = (d < HARD_CUT) ? 0.5f * (__cosf(PI_F * d * (1.0f / HARD_CUT)) + 1.0f) : 0.0f;
            float z   = (inv - muj) * isj;
            float e   = __expf(-0.5f * z * z) * cut;
            s_coef[pp][j]      = e;
            s_coef[pp][20 + j] = e * nx * inv;
            s_coef[pp][40 + j] = e * ny * inv;
            s_coef[pp][60 + j] = e * nz * inv;
            *(float4*)&s_feat[pp][j * 4] = nf;
        }
        int cnt = min(16, end - (start + ch * 16));
        __syncthreads();

        have = 0;
        if (ch + 1 < nchunk) {
            int p0 = start + (ch + 1) * 16;
            if (pp < min(16, end - p0)) {
                int p = p0 + pp;
                nd = dist[p]; nx = coord[3 * p]; ny = coord[3 * p + 1]; nz = coord[3 * p + 2];
                int r = ps[p]; nf = ((const float4*)feat)[r * 20 + j];
                have = 1;
            }
        }

        for (int p = 0; p < cnt; p++) {
            float2 cf = *(const float2*)&s_coef[p][cs0];
            ull c0d = dup2(cf.x);
            ull c1d = dup2(cf.y);
            #pragma unroll
            for (int u = 0; u < 5; u++) {
                ull fv = *(const ull*)&s_feat[p][f0 + 2 * u];
                ffma2(acc[0][u], c0d, fv);
                ffma2(acc[1][u], c1d, fv);
            }
        }
    }

    int c  = cs0 / 20;
    int s0 = cs0 % 20;
    size_t rbase = (size_t)(a * 4 + c) * KTOT;
    #pragma unroll
    for (int i = 0; i < 2; i++) {
        size_t cb = rbase + (s0 + i) * 80 + f0;
        #pragma unroll
        for (int u = 0; u < 5; u++) {
            float2 v = unpack2(acc[i][u]);
            __nv_bfloat16 h0 = __float2bfloat16(v.x);
            __nv_bfloat16 l0 = __float2bfloat16(v.x - __bfloat162float(h0));
            __nv_bfloat16 h1 = __float2bfloat16(v.y);
            __nv_bfloat16 l1 = __float2bfloat16(v.y - __bfloat162float(h1));
            __nv_bfloat162 hh; hh.x = h0; hh.y = h1;
            __nv_bfloat162 ll; ll.x = l0; ll.y = l1;
            *(__nv_bfloat162*)&g_env_hi[cb + 2 * u] = hh;
            *(__nv_bfloat162*)&g_env_lo[cb + 2 * u] = ll;
        }
    }

    {
        int c2 = tid / 80;   // 0..3
        int f  = tid % 80;
        float v = (c2 == 0) ? feat[a * 80 + f] : 0.0f;
        __nv_bfloat16 h = __float2bfloat16(v);
        __nv_bfloat16 l = __float2bfloat16(v - __bfloat162float(h));
        size_t off = (size_t)(a * 4 + c2) * KTOT + 1600 + f;
        g_env_hi[off] = h;
        g_env_lo[off] = l;
    }
}

// ---------------- K2: bf16-split GEMM via mma.sync + fused epilogue ----------------
// 256 threads = 8 warps: warp (wid>>1) owns 32 M-rows, (wid&1) owns 40 N-cols.
// Stage: A_hi 16K | A_lo 16K | B_hi 10K | B_lo 10K (XOR-swizzled 16B segs), x2 buffers.
__device__ __forceinline__ void load_stage(uint32_t sstage, int m0, int kc, int tid) {
    #pragma unroll
    for (int i = 0; i < 4; i++) {
        int u = tid + i * 256;                 // 1024: 128 rows x 8 segs
        int r = u >> 3, sg = u & 7;
        uint32_t so = (uint32_t)(r * 128 + ((sg ^ (r & 7)) * 16));
        const char* gh = (const char*)(g_env_hi + (size_t)(m0 + r) * KTOT + kc) + sg * 16;
        const char* gl = (const char*)(g_env_lo + (size_t)(m0 + r) * KTOT + kc) + sg * 16;
        CP16(sstage + OFF_AH + so, gh);
        CP16(sstage + OFF_AL + so, gl);
    }
    #pragma unroll
    for (int i = 0; i < 3; i++) {
        int u = tid + i * 256;                 // 640: 80 rows x 8 segs
        if (u < 640) {
            int r = u >> 3, sg = u & 7;
            uint32_t so = (uint32_t)(r * 128 + ((sg ^ (r & 7)) * 16));
            const char* gh = (const char*)(g_w2h + (size_t)r * KTOT + kc) + sg * 16;
            const char* gl = (const char*)(g_w2l + (size_t)r * KTOT + kc) + sg * 16;
            CP16(sstage + OFF_BH + so, gh);
            CP16(sstage + OFF_BL + so, gl);
        }
    }
}

__global__ __launch_bounds__(256, 1)
void gemm_kernel(const float* __restrict__ selfb, const float* __restrict__ vecs,
                 float* __restrict__ out, int n_atoms)
{
    extern __shared__ __align__(1024) char smem[];
    uint32_t sb = smem_u32(smem);
    int tid  = threadIdx.x;
    int lane = tid & 31;
    int wid  = tid >> 5;
    int m0   = blockIdx.x * 128;
    int m0w  = (wid >> 1) * 32;
    int n0w  = (wid & 1) * 40;

    // per-lane ldmatrix row bytes (swizzle row-index = lane&7 for all)
    int rA_loc = (lane & 7) + ((lane >> 3) & 1) * 8;
    uint32_t rowA0 = (uint32_t)((m0w + rA_loc) * 128);
    uint32_t rowA1 = rowA0 + 16 * 128;
    int rB_loc = (lane & 7) + ((lane >> 4) & 1) * 8;
    uint32_t rowB0 = (uint32_t)((n0w + rB_loc) * 128);
    uint32_t rowB1 = rowB0 + 16 * 128;
    uint32_t rowB2 = (uint32_t)((n0w + 32 + (lane & 7)) * 128);

    float acc[2][5][4];
    #pragma unroll
    for (int mt = 0; mt < 2; mt++)
        #pragma unroll
        for (int nt = 0; nt < 5; nt++)
            #pragma unroll
            for (int q = 0; q < 4; q++) acc[mt][nt][q] = 0.0f;

    load_stage(sb, m0, 0, tid);              CP_COMMIT();
    load_stage(sb + STG_BYTES, m0, KCH, tid); CP_COMMIT();

    for (int c = 0; c < NCH; c++) {
        if (c < NCH - 1) CP_WAIT1(); else CP_WAIT0();
        __syncthreads();

        uint32_t st  = sb + (uint32_t)((c & 1) * STG_BYTES);
        uint32_t sAH = st + OFF_AH, sAL = st + OFF_AL;
        uint32_t sBH = st + OFF_BH, sBL = st + OFF_BL;

        #pragma unroll
        for (int ks = 0; ks < 4; ks++) {
            uint32_t swA = (uint32_t)((((ks * 2) + (lane >> 4)) ^ (lane & 7)) * 16);
            uint32_t swB = (uint32_t)((((ks * 2) + ((lane >> 3) & 1)) ^ (lane & 7)) * 16);
            unsigned aH[2][4], aL[2][4], bH[10], bL[10];
            ldsm4(aH[0], sAH + rowA0 + swA);
            ldsm4(aH[1], sAH + rowA1 + swA);
            ldsm4(aL[0], sAL + rowA0 + swA);
            ldsm4(aL[1], sAL + rowA1 + swA);
            ldsm4(bH + 0, sBH + rowB0 + swB);
            ldsm4(bH + 4, sBH + rowB1 + swB);
            ldsm2(bH + 8, sBH + rowB2 + swB);
            ldsm4(bL + 0, sBL + rowB0 + swB);
            ldsm4(bL + 4, sBL + rowB1 + swB);
            ldsm2(bL + 8, sBL + rowB2 + swB);
            #pragma unroll
            for (int mt = 0; mt < 2; mt++)
                #pragma unroll
                for (int nt = 0; nt < 5; nt++) {
                    mma16816(acc[mt][nt], aH[mt], bH + 2 * nt);
                    mma16816(acc[mt][nt], aL[mt], bH + 2 * nt);
                    mma16816(acc[mt][nt], aH[mt], bL + 2 * nt);
                }
        }
        __syncthreads();
        if (c + 2 < NCH) { load_stage(sb + (uint32_t)((c & 1) * STG_BYTES), m0, (c + 2) * KCH, tid); CP_COMMIT(); }
    }

    // write accumulators to smem C[128][80]
    float* C = (float*)smem;
    int grp  = lane >> 2;
    int col0 = (lane & 3) * 2;
    #pragma unroll
    for (int mt = 0; mt < 2; mt++) {
        int r0 = m0w + mt * 16 + grp;
        #pragma unroll
        for (int nt = 0; nt < 5; nt++) {
            int cc = n0w + nt * 8 + col0;
            *(float2*)&C[r0 * 80 + cc]       = make_float2(acc[mt][nt][0], acc[mt][nt][1]);
            *(float2*)&C[(r0 + 8) * 80 + cc] = make_float2(acc[mt][nt][2], acc[mt][nt][3]);
        }
    }
    __syncthreads();

    #pragma unroll
    for (int u = tid; u < 2560; u += 256) {
        int al = u / 80, o = u % 80;
        int a = (m0 >> 2) + al;
        if (a < n_atoms) {
            float s0 = C[(al * 4 + 0) * 80 + o];
            float x  = C[(al * 4 + 1) * 80 + o];
            float y  = C[(al * 4 + 2) * 80 + o];
            float z  = C[(al * 4 + 3) * 80 + o];
            out[a * 80 + o] = s0 + selfb[o]
                + vecs[o] * sqrtf(fmaf(x, x, fmaf(y, y, z * z)) + 1e-30f);
        }
    }
}

// ---------------- launch ----------------
extern "C" void kernel_launch(void* const* d_in, const int* in_sizes, int n_in,
                              void* d_out, int out_size) {
    const float* feat  = (const float*)d_in[0];
    const float* dist  = (const float*)d_in[1];
    const float* coord = (const float*)d_in[2];
    const float* iw    = (const float*)d_in[3];
    const float* selfw = (const float*)d_in[4];
    const float* selfb = (const float*)d_in[5];
    const float* vecs  = (const float*)d_in[6];
    const float* mu    = (const float*)d_in[7];
    const float* sigma = (const float*)d_in[8];
    const int*   pf    = (const int*)d_in[9];
    const int*   ps    = (const int*)d_in[10];
    int n_pairs = in_sizes[9];
    int n_atoms = in_sizes[0] / 80;
    float* out = (float*)d_out;

    static int smem_set = 0;
    if (!smem_set) {
        cudaFuncSetAttribute(gemm_kernel, cudaFuncAttributeMaxDynamicSharedMemorySize,
                             2 * STG_BYTES);
        smem_set = 1;
    }

    build_w_kernel<<<(80 * KTOT + 255) / 256, 256>>>(iw, selfw);
    envsum_kernel<<<n_atoms, 320>>>(feat, dist, coord, mu, sigma, pf, ps, n_pairs);
    int mtiles = (n_atoms * 4 + 127) / 128;
    gemm_kernel<<<mtiles, 256, 2 * STG_BYTES>>>(selfb, vecs, out, n_atoms);
}